// round 1
// baseline (speedup 1.0000x reference)
#include <cuda_runtime.h>
#include <math.h>

#define BB 16
#define NN 4096
#define HH 512
#define NHEAD 8
#define MM 512
#define LNEPS 1e-5f

// ---------------- static scratch (no allocations allowed) ----------------
__device__ float g_ppart[BB * 32 * HH];
__device__ float g_pooled[BB * HH];
__device__ float g_gate[BB];
__device__ float g_sal[BB * NN];
__device__ int   g_cnt[BB];
__device__ int   g_idx[BB * MM];
__device__ float g_sel[(size_t)BB * MM * HH];
__device__ float g_qkv[(size_t)BB * MM * 3 * HH];
__device__ float g_scores[(size_t)BB * NHEAD * MM * MM];
__device__ float g_attn[(size_t)BB * MM * HH];
__device__ float g_rel[(size_t)BB * MM * HH];

// ---------------- block reductions (128 threads = 4 warps) ----------------
__device__ __forceinline__ float bred_sum(float v, float* sh) {
#pragma unroll
    for (int o = 16; o; o >>= 1) v += __shfl_down_sync(0xffffffffu, v, o);
    int tid = threadIdx.x;
    if ((tid & 31) == 0) sh[tid >> 5] = v;
    __syncthreads();
    if (tid == 0) sh[0] = sh[0] + sh[1] + sh[2] + sh[3];
    __syncthreads();
    float r = sh[0];
    __syncthreads();
    return r;
}

__device__ __forceinline__ float bred_max(float v, float* sh) {
#pragma unroll
    for (int o = 16; o; o >>= 1) v = fmaxf(v, __shfl_down_sync(0xffffffffu, v, o));
    int tid = threadIdx.x;
    if ((tid & 31) == 0) sh[tid >> 5] = v;
    __syncthreads();
    if (tid == 0) sh[0] = fmaxf(fmaxf(sh[0], sh[1]), fmaxf(sh[2], sh[3]));
    __syncthreads();
    float r = sh[0];
    __syncthreads();
    return r;
}

// ---------------- small kernels ----------------
__global__ void k_zero() {
    int t = blockIdx.x * blockDim.x + threadIdx.x;
    if (t < BB) g_cnt[t] = 0;
}

// partial sums over 128-token chunks (deterministic, no atomics)
__global__ void k_pool1(const float* __restrict__ tok) {
    int b = blockIdx.x, c = blockIdx.y, h = threadIdx.x;
    const float* p = tok + ((size_t)(b * NN + c * 128)) * HH + h;
    float s = 0.f;
#pragma unroll 8
    for (int n = 0; n < 128; n++) s += p[(size_t)n * HH];
    g_ppart[(b * 32 + c) * HH + h] = s;
}

__global__ void k_pool2() {
    int b = blockIdx.x, h = threadIdx.x;
    float s = 0.f;
#pragma unroll
    for (int c = 0; c < 32; c++) s += g_ppart[(b * 32 + c) * HH + h];
    g_pooled[b * HH + h] = s * (1.f / NN);
}

// gate = sigmoid(LN(pooled) . gate_w + gate_b)
__global__ void k_gate(const float* __restrict__ lg, const float* __restrict__ lb,
                       const float* __restrict__ w, const float* __restrict__ wb) {
    __shared__ float sh[4];
    int b = blockIdx.x, tid = threadIdx.x;
    const float* x = g_pooled + b * HH;
    float v0 = x[tid], v1 = x[tid + 128], v2 = x[tid + 256], v3 = x[tid + 384];
    float s = bred_sum(v0 + v1 + v2 + v3, sh);
    float q = bred_sum(v0 * v0 + v1 * v1 + v2 * v2 + v3 * v3, sh);
    float mean = s * (1.f / HH);
    float var = q * (1.f / HH) - mean * mean;
    float rstd = rsqrtf(var + LNEPS);
    float d = ((v0 - mean) * rstd * lg[tid] + lb[tid]) * w[tid]
            + ((v1 - mean) * rstd * lg[tid + 128] + lb[tid + 128]) * w[tid + 128]
            + ((v2 - mean) * rstd * lg[tid + 256] + lb[tid + 256]) * w[tid + 256]
            + ((v3 - mean) * rstd * lg[tid + 384] + lb[tid + 384]) * w[tid + 384];
    d = bred_sum(d, sh);
    if (tid == 0) g_gate[b] = 1.f / (1.f + expf(-(d + wb[0])));
}

// salience[t] = LN(token_t) . sal_w + sal_b   (one block per token)
__global__ void k_sal(const float* __restrict__ tok, const float* __restrict__ lg,
                      const float* __restrict__ lb, const float* __restrict__ w,
                      const float* __restrict__ wb) {
    __shared__ float sh[4];
    int t = blockIdx.x, tid = threadIdx.x;
    const float* x = tok + (size_t)t * HH;
    float v0 = x[tid], v1 = x[tid + 128], v2 = x[tid + 256], v3 = x[tid + 384];
    float s = bred_sum(v0 + v1 + v2 + v3, sh);
    float q = bred_sum(v0 * v0 + v1 * v1 + v2 * v2 + v3 * v3, sh);
    float mean = s * (1.f / HH);
    float var = q * (1.f / HH) - mean * mean;
    float rstd = rsqrtf(var + LNEPS);
    float d = ((v0 - mean) * rstd * lg[tid] + lb[tid]) * w[tid]
            + ((v1 - mean) * rstd * lg[tid + 128] + lb[tid + 128]) * w[tid + 128]
            + ((v2 - mean) * rstd * lg[tid + 256] + lb[tid + 256]) * w[tid + 256]
            + ((v3 - mean) * rstd * lg[tid + 384] + lb[tid + 384]) * w[tid + 384];
    d = bred_sum(d, sh);
    if (tid == 0) g_sal[t] = d + wb[0];
}

// exact top-MM by rank counting (ties -> lower index, matches jax top_k set)
__global__ void k_topk() {
    __shared__ float sh[NN];
    int b = blockIdx.x;
    for (int j = threadIdx.x; j < NN; j += 256) sh[j] = g_sal[b * NN + j];
    __syncthreads();
    int i = blockIdx.y * 256 + threadIdx.x;
    float si = sh[i];
    int cnt = 0;
    for (int j = 0; j < NN; j++) {
        float sj = sh[j];
        cnt += (sj > si) || (sj == si && j < i);
    }
    if (cnt < MM) {
        int p = atomicAdd(&g_cnt[b], 1);
        g_idx[b * MM + p] = i;
    }
}

__global__ void k_gather(const float* __restrict__ tok) {
    int t = blockIdx.x;           // b*MM + m
    int b = t >> 9;
    const float4* src = (const float4*)(tok + ((size_t)b * NN + g_idx[t]) * HH);
    float4* dst = (float4*)(g_sel + (size_t)t * HH);
    dst[threadIdx.x] = src[threadIdx.x];
}

// ---------------- generic tiled SGEMM ----------------
// BT=1: C[m,n] = scale * sum_k A[m,k]*B[n,k] + bias[n]
// BT=0: C[m,n] = scale * sum_k A[m,k]*B[k,n] + bias[n]
// batch z decomposed as (z/zInner, z%zInner) with two stride pairs.
template <int BT>
__global__ void k_gemm(const float* __restrict__ A, const float* __restrict__ Bm,
                       const float* __restrict__ bias, float* __restrict__ C,
                       int K, int lda, int ldb, int ldc, int zInner,
                       long aS1, long aS2, long bS1, long bS2, long cS1, long cS2,
                       float scale) {
    __shared__ float As[16][64];
    __shared__ float Bs[16][64];
    int z = blockIdx.z;
    const float* Ab = A + (long)(z / zInner) * aS1 + (long)(z % zInner) * aS2;
    const float* Bb = Bm + (long)(z / zInner) * bS1 + (long)(z % zInner) * bS2;
    float* Cb = C + (long)(z / zInner) * cS1 + (long)(z % zInner) * cS2;
    int m0 = blockIdx.y * 64, n0 = blockIdx.x * 64;
    int tid = threadIdx.x;
    int tx = tid & 15, ty = tid >> 4;
    int lr = tid >> 2;
    int lk = (tid & 3) << 2;
    float acc[4][4] = {{0.f}};

    for (int k0 = 0; k0 < K; k0 += 16) {
        float4 av = *(const float4*)(Ab + (long)(m0 + lr) * lda + k0 + lk);
        As[lk + 0][lr] = av.x; As[lk + 1][lr] = av.y;
        As[lk + 2][lr] = av.z; As[lk + 3][lr] = av.w;
        if (BT) {
            float4 bv = *(const float4*)(Bb + (long)(n0 + lr) * ldb + k0 + lk);
            Bs[lk + 0][lr] = bv.x; Bs[lk + 1][lr] = bv.y;
            Bs[lk + 2][lr] = bv.z; Bs[lk + 3][lr] = bv.w;
        } else {
            int kk = tid >> 4;
            int nn = (tid & 15) << 2;
            float4 bv = *(const float4*)(Bb + (long)(k0 + kk) * ldb + n0 + nn);
            *(float4*)&Bs[kk][nn] = bv;
        }
        __syncthreads();
#pragma unroll
        for (int k = 0; k < 16; k++) {
            float4 a4 = *(const float4*)&As[k][ty << 2];
            float4 b4 = *(const float4*)&Bs[k][tx << 2];
            acc[0][0] += a4.x * b4.x; acc[0][1] += a4.x * b4.y;
            acc[0][2] += a4.x * b4.z; acc[0][3] += a4.x * b4.w;
            acc[1][0] += a4.y * b4.x; acc[1][1] += a4.y * b4.y;
            acc[1][2] += a4.y * b4.z; acc[1][3] += a4.y * b4.w;
            acc[2][0] += a4.z * b4.x; acc[2][1] += a4.z * b4.y;
            acc[2][2] += a4.z * b4.z; acc[2][3] += a4.z * b4.w;
            acc[3][0] += a4.w * b4.x; acc[3][1] += a4.w * b4.y;
            acc[3][2] += a4.w * b4.z; acc[3][3] += a4.w * b4.w;
        }
        __syncthreads();
    }
    float b0 = 0.f, b1 = 0.f, b2 = 0.f, b3 = 0.f;
    if (bias) {
        int nb = n0 + (tx << 2);
        b0 = bias[nb]; b1 = bias[nb + 1]; b2 = bias[nb + 2]; b3 = bias[nb + 3];
    }
#pragma unroll
    for (int i = 0; i < 4; i++) {
        float4 o;
        o.x = acc[i][0] * scale + b0;
        o.y = acc[i][1] * scale + b1;
        o.z = acc[i][2] * scale + b2;
        o.w = acc[i][3] * scale + b3;
        *(float4*)(Cb + (long)(m0 + (ty << 2) + i) * ldc + n0 + (tx << 2)) = o;
    }
}

__global__ void k_softmax() {
    __shared__ float sh[4];
    size_t row = blockIdx.x;
    float* p = g_scores + row * MM;
    int tid = threadIdx.x;
    float v0 = p[tid], v1 = p[tid + 128], v2 = p[tid + 256], v3 = p[tid + 384];
    float mx = bred_max(fmaxf(fmaxf(v0, v1), fmaxf(v2, v3)), sh);
    float e0 = __expf(v0 - mx), e1 = __expf(v1 - mx), e2 = __expf(v2 - mx), e3 = __expf(v3 - mx);
    float sum = bred_sum(e0 + e1 + e2 + e3, sh);
    float inv = 1.f / sum;
    p[tid] = e0 * inv; p[tid + 128] = e1 * inv;
    p[tid + 256] = e2 * inv; p[tid + 384] = e3 * inv;
}

// y = LN(sel + rel) with rel_ln, in place into g_rel
__global__ void k_lnres(const float* __restrict__ lg, const float* __restrict__ lb) {
    __shared__ float sh[4];
    int t = blockIdx.x, tid = threadIdx.x;
    float* r = g_rel + (size_t)t * HH;
    const float* s = g_sel + (size_t)t * HH;
    float v0 = s[tid] + r[tid];
    float v1 = s[tid + 128] + r[tid + 128];
    float v2 = s[tid + 256] + r[tid + 256];
    float v3 = s[tid + 384] + r[tid + 384];
    float su = bred_sum(v0 + v1 + v2 + v3, sh);
    float q = bred_sum(v0 * v0 + v1 * v1 + v2 * v2 + v3 * v3, sh);
    float mean = su * (1.f / HH);
    float var = q * (1.f / HH) - mean * mean;
    float rstd = rsqrtf(var + LNEPS);
    r[tid]       = (v0 - mean) * rstd * lg[tid]       + lb[tid];
    r[tid + 128] = (v1 - mean) * rstd * lg[tid + 128] + lb[tid + 128];
    r[tid + 256] = (v2 - mean) * rstd * lg[tid + 256] + lb[tid + 256];
    r[tid + 384] = (v3 - mean) * rstd * lg[tid + 384] + lb[tid + 384];
}

__global__ void k_scatter(float* __restrict__ out) {
    int t = blockIdx.x, tid = threadIdx.x;
    int b = t >> 9;
    float gp = g_gate[b];
    float* dst = out + ((size_t)b * NN + g_idx[t]) * HH;
    const float* y = g_rel + (size_t)t * HH;
    dst[tid]       += gp * y[tid];
    dst[tid + 128] += gp * y[tid + 128];
    dst[tid + 256] += gp * y[tid + 256];
    dst[tid + 384] += gp * y[tid + 384];
}

// ---------------- launch ----------------
extern "C" void kernel_launch(void* const* d_in, const int* in_sizes, int n_in,
                              void* d_out, int out_size) {
    const float* tok        = (const float*)d_in[0];
    const float* gate_ln_g  = (const float*)d_in[1];
    const float* gate_ln_b  = (const float*)d_in[2];
    const float* gate_w     = (const float*)d_in[3];
    const float* gate_b     = (const float*)d_in[4];
    const float* sal_ln_g   = (const float*)d_in[5];
    const float* sal_ln_b   = (const float*)d_in[6];
    const float* sal_w      = (const float*)d_in[7];
    const float* sal_b      = (const float*)d_in[8];
    const float* in_proj_w  = (const float*)d_in[9];
    const float* in_proj_b  = (const float*)d_in[10];
    const float* out_proj_w = (const float*)d_in[11];
    const float* out_proj_b = (const float*)d_in[12];
    const float* rel_ln_g   = (const float*)d_in[13];
    const float* rel_ln_b   = (const float*)d_in[14];
    float* out = (float*)d_out;

    void *p_sel_v, *p_qkv_v, *p_scores_v, *p_attn_v, *p_rel_v;
    cudaGetSymbolAddress(&p_sel_v, g_sel);
    cudaGetSymbolAddress(&p_qkv_v, g_qkv);
    cudaGetSymbolAddress(&p_scores_v, g_scores);
    cudaGetSymbolAddress(&p_attn_v, g_attn);
    cudaGetSymbolAddress(&p_rel_v, g_rel);
    float* p_sel = (float*)p_sel_v;
    float* p_qkv = (float*)p_qkv_v;
    float* p_scores = (float*)p_scores_v;
    float* p_attn = (float*)p_attn_v;
    float* p_rel = (float*)p_rel_v;

    // out starts as a copy of tokens
    cudaMemcpyAsync(out, tok, (size_t)BB * NN * HH * sizeof(float),
                    cudaMemcpyDeviceToDevice);

    k_zero<<<1, 32>>>();
    k_pool1<<<dim3(BB, 32), 512>>>(tok);
    k_pool2<<<BB, 512>>>();
    k_gate<<<BB, 128>>>(gate_ln_g, gate_ln_b, gate_w, gate_b);
    k_sal<<<BB * NN, 128>>>(tok, sal_ln_g, sal_ln_b, sal_w, sal_b);
    k_topk<<<dim3(BB, NN / 256), 256>>>();
    k_gather<<<BB * MM, 128>>>(tok);

    // qkv = sel @ in_proj_w^T + in_proj_b   (8192 x 1536, K=512)
    k_gemm<1><<<dim3(3 * HH / 64, BB * MM / 64, 1), 256>>>(
        p_sel, in_proj_w, in_proj_b, p_qkv,
        HH, HH, HH, 3 * HH, 1, 0L, 0L, 0L, 0L, 0L, 0L, 1.f);

    // scores = q @ k^T / 8   per (b,h): M=512, N=512, K=64
    k_gemm<1><<<dim3(MM / 64, MM / 64, BB * NHEAD), 256>>>(
        p_qkv, p_qkv + HH, (const float*)0, p_scores,
        64, 3 * HH, 3 * HH, MM, NHEAD,
        (long)MM * 3 * HH, 64L, (long)MM * 3 * HH, 64L,
        (long)NHEAD * MM * MM, (long)MM * MM, 0.125f);

    k_softmax<<<BB * NHEAD * MM, 128>>>();

    // attn_out = attn @ v   per (b,h): M=512, N=64, K=512
    k_gemm<0><<<dim3(1, MM / 64, BB * NHEAD), 256>>>(
        p_scores, p_qkv + 2 * HH, (const float*)0, p_attn,
        MM, MM, 3 * HH, HH, NHEAD,
        (long)NHEAD * MM * MM, (long)MM * MM,
        (long)MM * 3 * HH, 64L,
        (long)MM * HH, 64L, 1.f);

    // rel = attn_out @ out_proj_w^T + out_proj_b   (8192 x 512, K=512)
    k_gemm<1><<<dim3(HH / 64, BB * MM / 64, 1), 256>>>(
        p_attn, out_proj_w, out_proj_b, p_rel,
        HH, HH, HH, HH, 1, 0L, 0L, 0L, 0L, 0L, 0L, 1.f);

    k_lnres<<<BB * MM, 128>>>(rel_ln_g, rel_ln_b);
    k_scatter<<<BB * MM, 128>>>(out);
}

// round 4
// speedup vs baseline: 2.0903x; 2.0903x over previous
#include <cuda_runtime.h>
#include <stdint.h>
#include <math.h>

#define BB 16
#define NN 4096
#define HH 512
#define NHEAD 8
#define MM 512
#define LNEPS 1e-5f

// ---------------- static scratch (no allocations allowed) ----------------
__device__ float g_ppart[BB * 32 * HH];
__device__ float g_pooled[BB * HH];
__device__ float g_gate[BB];
__device__ float g_sal[BB * NN];
__device__ int   g_cnt[BB];
__device__ int   g_idx[BB * MM];
__device__ float g_sel[(size_t)BB * MM * HH];
__device__ float g_qkv[(size_t)BB * MM * 3 * HH];
__device__ float g_scores[(size_t)BB * NHEAD * MM * MM];
__device__ float g_vt[(size_t)BB * NHEAD * 64 * MM];
__device__ float g_attn[(size_t)BB * MM * HH];
__device__ float g_rel[(size_t)BB * MM * HH];

// ---------------- block reductions (128 threads = 4 warps) ----------------
__device__ __forceinline__ float bred_sum(float v, float* sh) {
#pragma unroll
    for (int o = 16; o; o >>= 1) v += __shfl_down_sync(0xffffffffu, v, o);
    int tid = threadIdx.x;
    if ((tid & 31) == 0) sh[tid >> 5] = v;
    __syncthreads();
    if (tid == 0) sh[0] = sh[0] + sh[1] + sh[2] + sh[3];
    __syncthreads();
    float r = sh[0];
    __syncthreads();
    return r;
}

__device__ __forceinline__ float bred_max(float v, float* sh) {
#pragma unroll
    for (int o = 16; o; o >>= 1) v = fmaxf(v, __shfl_down_sync(0xffffffffu, v, o));
    int tid = threadIdx.x;
    if ((tid & 31) == 0) sh[tid >> 5] = v;
    __syncthreads();
    if (tid == 0) sh[0] = fmaxf(fmaxf(sh[0], sh[1]), fmaxf(sh[2], sh[3]));
    __syncthreads();
    float r = sh[0];
    __syncthreads();
    return r;
}

// ---------------- small kernels ----------------
__global__ void k_zero() {
    int t = blockIdx.x * blockDim.x + threadIdx.x;
    if (t < BB) g_cnt[t] = 0;
}

__global__ void k_pool1(const float* __restrict__ tok) {
    int b = blockIdx.x, c = blockIdx.y, h = threadIdx.x;
    const float* p = tok + ((size_t)(b * NN + c * 128)) * HH + h;
    float s = 0.f;
#pragma unroll 8
    for (int n = 0; n < 128; n++) s += p[(size_t)n * HH];
    g_ppart[(b * 32 + c) * HH + h] = s;
}

__global__ void k_pool2() {
    int b = blockIdx.x, h = threadIdx.x;
    float s = 0.f;
#pragma unroll
    for (int c = 0; c < 32; c++) s += g_ppart[(b * 32 + c) * HH + h];
    g_pooled[b * HH + h] = s * (1.f / NN);
}

__global__ void k_gate(const float* __restrict__ lg, const float* __restrict__ lb,
                       const float* __restrict__ w, const float* __restrict__ wb) {
    __shared__ float sh[4];
    int b = blockIdx.x, tid = threadIdx.x;
    const float* x = g_pooled + b * HH;
    float v0 = x[tid], v1 = x[tid + 128], v2 = x[tid + 256], v3 = x[tid + 384];
    float s = bred_sum(v0 + v1 + v2 + v3, sh);
    float q = bred_sum(v0 * v0 + v1 * v1 + v2 * v2 + v3 * v3, sh);
    float mean = s * (1.f / HH);
    float var = q * (1.f / HH) - mean * mean;
    float rstd = rsqrtf(var + LNEPS);
    float d = ((v0 - mean) * rstd * lg[tid] + lb[tid]) * w[tid]
            + ((v1 - mean) * rstd * lg[tid + 128] + lb[tid + 128]) * w[tid + 128]
            + ((v2 - mean) * rstd * lg[tid + 256] + lb[tid + 256]) * w[tid + 256]
            + ((v3 - mean) * rstd * lg[tid + 384] + lb[tid + 384]) * w[tid + 384];
    d = bred_sum(d, sh);
    if (tid == 0) g_gate[b] = 1.f / (1.f + expf(-(d + wb[0])));
}

__global__ void k_sal(const float* __restrict__ tok, const float* __restrict__ lg,
                      const float* __restrict__ lb, const float* __restrict__ w,
                      const float* __restrict__ wb) {
    __shared__ float sh[4];
    int t = blockIdx.x, tid = threadIdx.x;
    const float* x = tok + (size_t)t * HH;
    float v0 = x[tid], v1 = x[tid + 128], v2 = x[tid + 256], v3 = x[tid + 384];
    float s = bred_sum(v0 + v1 + v2 + v3, sh);
    float q = bred_sum(v0 * v0 + v1 * v1 + v2 * v2 + v3 * v3, sh);
    float mean = s * (1.f / HH);
    float var = q * (1.f / HH) - mean * mean;
    float rstd = rsqrtf(var + LNEPS);
    float d = ((v0 - mean) * rstd * lg[tid] + lb[tid]) * w[tid]
            + ((v1 - mean) * rstd * lg[tid + 128] + lb[tid + 128]) * w[tid + 128]
            + ((v2 - mean) * rstd * lg[tid + 256] + lb[tid + 256]) * w[tid + 256]
            + ((v3 - mean) * rstd * lg[tid + 384] + lb[tid + 384]) * w[tid + 384];
    d = bred_sum(d, sh);
    if (tid == 0) g_sal[t] = d + wb[0];
}

__global__ void k_topk() {
    __shared__ float sh[NN];
    int b = blockIdx.x;
    for (int j = threadIdx.x; j < NN; j += 256) sh[j] = g_sal[b * NN + j];
    __syncthreads();
    int i = blockIdx.y * 256 + threadIdx.x;
    float si = sh[i];
    int cnt = 0;
    for (int j = 0; j < NN; j++) {
        float sj = sh[j];
        cnt += (sj > si) || (sj == si && j < i);
    }
    if (cnt < MM) {
        int p = atomicAdd(&g_cnt[b], 1);
        g_idx[b * MM + p] = i;
    }
}

__global__ void k_gather(const float* __restrict__ tok) {
    int t = blockIdx.x;
    int b = t >> 9;
    const float4* src = (const float4*)(tok + ((size_t)b * NN + g_idx[t]) * HH);
    float4* dst = (float4*)(g_sel + (size_t)t * HH);
    dst[threadIdx.x] = src[threadIdx.x];
}

// ---------------- TF32 tensor-core GEMM ----------------
__device__ __forceinline__ uint32_t f2tf(float f) {
    uint32_t u;
    asm("cvt.rna.tf32.f32 %0, %1;" : "=r"(u) : "f"(f));
    return u;
}

__device__ __forceinline__ void mma8(float* d, const uint32_t* a, const uint32_t* b) {
    asm volatile(
        "mma.sync.aligned.m16n8k8.row.col.f32.tf32.tf32.f32 "
        "{%0,%1,%2,%3}, {%4,%5,%6,%7}, {%8,%9}, {%0,%1,%2,%3};"
        : "+f"(d[0]), "+f"(d[1]), "+f"(d[2]), "+f"(d[3])
        : "r"(a[0]), "r"(a[1]), "r"(a[2]), "r"(a[3]), "r"(b[0]), "r"(b[1]));
}

// C[m,n] = scale * sum_k A[m,k]*B[n,k] + bias[n]
// A: [M][K] stride lda; B: [N][K] stride ldb (i.e. B^T of math B).
// Batch z = z1*zInner + z2 with strides (aS1,aS2) etc.
template <int MT, int NT, int BWM, int BWN>
__global__ void __launch_bounds__(256, 2)
k_gemm_tc(const float* __restrict__ A, const float* __restrict__ B,
          const float* __restrict__ bias, float* __restrict__ C,
          int K, int lda, int ldb, int ldc, int zInner,
          long aS1, long aS2, long bS1, long bS2, long cS1, long cS2,
          float scale) {
    constexpr int WM = MT / BWM, WN = NT / BWN;
    constexpr int AM = WM / 16, BN = WN / 8;
    __shared__ uint32_t As[MT][36];
    __shared__ uint32_t Bs[NT][36];

    int z = blockIdx.z;
    const float* Ab = A + (long)(z / zInner) * aS1 + (long)(z % zInner) * aS2;
    const float* Bb = B + (long)(z / zInner) * bS1 + (long)(z % zInner) * bS2;
    float* Cb = C + (long)(z / zInner) * cS1 + (long)(z % zInner) * cS2;

    int m0 = blockIdx.y * MT, n0 = blockIdx.x * NT;
    int tid = threadIdx.x, lane = tid & 31, wid = tid >> 5;
    int wm = (wid / BWN) * WM, wn = (wid % BWN) * WN;

    float acc[AM][BN][4];
#pragma unroll
    for (int i = 0; i < AM; i++)
#pragma unroll
        for (int j = 0; j < BN; j++) {
            acc[i][j][0] = 0.f; acc[i][j][1] = 0.f;
            acc[i][j][2] = 0.f; acc[i][j][3] = 0.f;
        }

    int lr = tid >> 3, lk = (tid & 7) << 2;

    for (int k0 = 0; k0 < K; k0 += 32) {
#pragma unroll
        for (int i = 0; i < MT / 32; i++) {
            float4 v = *(const float4*)(Ab + (long)(m0 + lr + 32 * i) * lda + k0 + lk);
            uint32_t* p = &As[lr + 32 * i][lk];
            p[0] = f2tf(v.x); p[1] = f2tf(v.y); p[2] = f2tf(v.z); p[3] = f2tf(v.w);
        }
#pragma unroll
        for (int i = 0; i < NT / 32; i++) {
            float4 v = *(const float4*)(Bb + (long)(n0 + lr + 32 * i) * ldb + k0 + lk);
            uint32_t* p = &Bs[lr + 32 * i][lk];
            p[0] = f2tf(v.x); p[1] = f2tf(v.y); p[2] = f2tf(v.z); p[3] = f2tf(v.w);
        }
        __syncthreads();
#pragma unroll
        for (int kk = 0; kk < 32; kk += 8) {
            uint32_t af[AM][4];
#pragma unroll
            for (int i = 0; i < AM; i++) {
                int r = wm + i * 16 + (lane >> 2);
                int c = kk + (lane & 3);
                af[i][0] = As[r][c];
                af[i][1] = As[r + 8][c];
                af[i][2] = As[r][c + 4];
                af[i][3] = As[r + 8][c + 4];
            }
            uint32_t bf[BN][2];
#pragma unroll
            for (int j = 0; j < BN; j++) {
                int nrow = wn + j * 8 + (lane >> 2);
                int c = kk + (lane & 3);
                bf[j][0] = Bs[nrow][c];
                bf[j][1] = Bs[nrow][c + 4];
            }
#pragma unroll
            for (int i = 0; i < AM; i++)
#pragma unroll
                for (int j = 0; j < BN; j++)
                    mma8(acc[i][j], af[i], bf[j]);
        }
        __syncthreads();
    }
#pragma unroll
    for (int i = 0; i < AM; i++) {
        int r0 = m0 + wm + i * 16 + (lane >> 2);
#pragma unroll
        for (int j = 0; j < BN; j++) {
            int c0 = n0 + wn + j * 8 + ((lane & 3) << 1);
            float b0 = 0.f, b1 = 0.f;
            if (bias) { b0 = bias[c0]; b1 = bias[c0 + 1]; }
            float2 o0, o1;
            o0.x = acc[i][j][0] * scale + b0;
            o0.y = acc[i][j][1] * scale + b1;
            o1.x = acc[i][j][2] * scale + b0;
            o1.y = acc[i][j][3] * scale + b1;
            *(float2*)(Cb + (long)r0 * ldc + c0) = o0;
            *(float2*)(Cb + (long)(r0 + 8) * ldc + c0) = o1;
        }
    }
}

// transpose V chunk of qkv into g_vt[z][64][512]
__global__ void k_vt(const float* __restrict__ qkv) {
    __shared__ float t[32][65];
    int z = blockIdx.x, b = z >> 3, h = z & 7;
    int m0 = blockIdx.y << 5;
    int d = threadIdx.x & 63, ml = threadIdx.x >> 6;
    const float* src = qkv + (size_t)(b * MM + m0) * (3 * HH) + 2 * HH + h * 64 + d;
#pragma unroll
    for (int i = 0; i < 8; i++)
        t[ml + 4 * i][d] = src[(size_t)(ml + 4 * i) * (3 * HH)];
    __syncthreads();
    int m = threadIdx.x & 31, dl = threadIdx.x >> 5;
    float* dst = g_vt + (size_t)z * (64 * MM) + m0 + m;
#pragma unroll
    for (int j = 0; j < 8; j++)
        dst[(size_t)(dl + 8 * j) * MM] = t[m][dl + 8 * j];
}

__global__ void k_softmax() {
    __shared__ float sh[4];
    size_t row = blockIdx.x;
    float* p = g_scores + row * MM;
    int tid = threadIdx.x;
    float v0 = p[tid], v1 = p[tid + 128], v2 = p[tid + 256], v3 = p[tid + 384];
    float mx = bred_max(fmaxf(fmaxf(v0, v1), fmaxf(v2, v3)), sh);
    float e0 = __expf(v0 - mx), e1 = __expf(v1 - mx), e2 = __expf(v2 - mx), e3 = __expf(v3 - mx);
    float sum = bred_sum(e0 + e1 + e2 + e3, sh);
    float inv = 1.f / sum;
    p[tid] = e0 * inv; p[tid + 128] = e1 * inv;
    p[tid + 256] = e2 * inv; p[tid + 384] = e3 * inv;
}

__global__ void k_lnres(const float* __restrict__ lg, const float* __restrict__ lb) {
    __shared__ float sh[4];
    int t = blockIdx.x, tid = threadIdx.x;
    float* r = g_rel + (size_t)t * HH;
    const float* s = g_sel + (size_t)t * HH;
    float v0 = s[tid] + r[tid];
    float v1 = s[tid + 128] + r[tid + 128];
    float v2 = s[tid + 256] + r[tid + 256];
    float v3 = s[tid + 384] + r[tid + 384];
    float su = bred_sum(v0 + v1 + v2 + v3, sh);
    float q = bred_sum(v0 * v0 + v1 * v1 + v2 * v2 + v3 * v3, sh);
    float mean = su * (1.f / HH);
    float var = q * (1.f / HH) - mean * mean;
    float rstd = rsqrtf(var + LNEPS);
    r[tid]       = (v0 - mean) * rstd * lg[tid]       + lb[tid];
    r[tid + 128] = (v1 - mean) * rstd * lg[tid + 128] + lb[tid + 128];
    r[tid + 256] = (v2 - mean) * rstd * lg[tid + 256] + lb[tid + 256];
    r[tid + 384] = (v3 - mean) * rstd * lg[tid + 384] + lb[tid + 384];
}

__global__ void k_scatter(float* __restrict__ out) {
    int t = blockIdx.x, tid = threadIdx.x;
    int b = t >> 9;
    float gp = g_gate[b];
    float* dst = out + ((size_t)b * NN + g_idx[t]) * HH;
    const float* y = g_rel + (size_t)t * HH;
    dst[tid]       += gp * y[tid];
    dst[tid + 128] += gp * y[tid + 128];
    dst[tid + 256] += gp * y[tid + 256];
    dst[tid + 384] += gp * y[tid + 384];
}

// ---------------- launch ----------------
extern "C" void kernel_launch(void* const* d_in, const int* in_sizes, int n_in,
                              void* d_out, int out_size) {
    const float* tok        = (const float*)d_in[0];
    const float* gate_ln_g  = (const float*)d_in[1];
    const float* gate_ln_b  = (const float*)d_in[2];
    const float* gate_w     = (const float*)d_in[3];
    const float* gate_b     = (const float*)d_in[4];
    const float* sal_ln_g   = (const float*)d_in[5];
    const float* sal_ln_b   = (const float*)d_in[6];
    const float* sal_w      = (const float*)d_in[7];
    const float* sal_b      = (const float*)d_in[8];
    const float* in_proj_w  = (const float*)d_in[9];
    const float* in_proj_b  = (const float*)d_in[10];
    const float* out_proj_w = (const float*)d_in[11];
    const float* out_proj_b = (const float*)d_in[12];
    const float* rel_ln_g   = (const float*)d_in[13];
    const float* rel_ln_b   = (const float*)d_in[14];
    float* out = (float*)d_out;

    void *p_sel_v, *p_qkv_v, *p_scores_v, *p_attn_v, *p_rel_v, *p_vt_v;
    cudaGetSymbolAddress(&p_sel_v, g_sel);
    cudaGetSymbolAddress(&p_qkv_v, g_qkv);
    cudaGetSymbolAddress(&p_scores_v, g_scores);
    cudaGetSymbolAddress(&p_attn_v, g_attn);
    cudaGetSymbolAddress(&p_rel_v, g_rel);
    cudaGetSymbolAddress(&p_vt_v, g_vt);
    float* p_sel = (float*)p_sel_v;
    float* p_qkv = (float*)p_qkv_v;
    float* p_scores = (float*)p_scores_v;
    float* p_attn = (float*)p_attn_v;
    float* p_rel = (float*)p_rel_v;
    float* p_vt = (float*)p_vt_v;

    cudaMemcpyAsync(out, tok, (size_t)BB * NN * HH * sizeof(float),
                    cudaMemcpyDeviceToDevice);

    k_zero<<<1, 32>>>();
    k_pool1<<<dim3(BB, 32), 512>>>(tok);
    k_pool2<<<BB, 512>>>();
    k_gate<<<BB, 128>>>(gate_ln_g, gate_ln_b, gate_w, gate_b);
    k_sal<<<BB * NN, 128>>>(tok, sal_ln_g, sal_ln_b, sal_w, sal_b);
    k_topk<<<dim3(BB, NN / 256), 256>>>();
    k_gather<<<BB * MM, 128>>>(tok);

    // qkv = sel @ in_proj_w^T + in_proj_b : M=8192, N=1536, K=512
    k_gemm_tc<128, 128, 2, 4><<<dim3(12, 64, 1), 256>>>(
        p_sel, in_proj_w, in_proj_b, p_qkv,
        HH, HH, HH, 3 * HH, 1, 0L, 0L, 0L, 0L, 0L, 0L, 1.f);

    // scores = q @ k^T / 8 per (b,h): M=512, N=512, K=64
    k_gemm_tc<128, 128, 2, 4><<<dim3(4, 4, BB * NHEAD), 256>>>(
        p_qkv, p_qkv + HH, (const float*)0, p_scores,
        64, 3 * HH, 3 * HH, MM, NHEAD,
        (long)MM * 3 * HH, 64L, (long)MM * 3 * HH, 64L,
        (long)NHEAD * MM * MM, (long)MM * MM, 0.125f);

    k_softmax<<<BB * NHEAD * MM, 128>>>();
    k_vt<<<dim3(BB * NHEAD, MM / 32), 256>>>(p_qkv);

    // attn_out = attn @ v per (b,h): M=512, N=64, K=512 (B = V^T in [N][K])
    k_gemm_tc<128, 64, 4, 2><<<dim3(1, 4, BB * NHEAD), 256>>>(
        p_scores, p_vt, (const float*)0, p_attn,
        MM, MM, MM, HH, NHEAD,
        (long)NHEAD * MM * MM, (long)MM * MM,
        (long)NHEAD * 64 * MM, (long)64 * MM,
        (long)MM * HH, 64L, 1.f);

    // rel = attn_out @ out_proj_w^T + out_proj_b : M=8192, N=512, K=512
    k_gemm_tc<128, 128, 2, 4><<<dim3(4, 64, 1), 256>>>(
        p_attn, out_proj_w, out_proj_b, p_rel,
        HH, HH, HH, HH, 1, 0L, 0L, 0L, 0L, 0L, 0L, 1.f);

    k_lnres<<<BB * MM, 128>>>(rel_ln_g, rel_ln_b);
    k_scatter<<<BB * MM, 128>>>(out);
}

// round 6
// speedup vs baseline: 2.3854x; 1.1412x over previous
#include <cuda_runtime.h>
#include <cuda_bf16.h>
#include <stdint.h>
#include <math.h>

#define BB 16
#define NN 4096
#define HH 512
#define NHEAD 8
#define MM 512
#define LNEPS 1e-5f

// ---------------- static scratch (no allocations allowed) ----------------
__device__ float g_ppart[BB * 32 * HH];
__device__ float g_pooled[BB * HH];
__device__ float g_gate[BB];
__device__ float g_sal[BB * NN];
__device__ int   g_cnt[BB];
__device__ int   g_idx[BB * MM];
__device__ int   g_map[BB * NN];
__device__ float g_sel[(size_t)BB * MM * HH];
__device__ float g_qkv[(size_t)BB * MM * 3 * HH];
__device__ float g_scores[(size_t)BB * NHEAD * MM * MM];
__device__ float g_vt[(size_t)BB * NHEAD * 64 * MM];
__device__ float g_attn[(size_t)BB * MM * HH];
__device__ float g_rel[(size_t)BB * MM * HH];

// ---------------- block reductions (128 threads = 4 warps) ----------------
__device__ __forceinline__ float bred_sum(float v, float* sh) {
#pragma unroll
    for (int o = 16; o; o >>= 1) v += __shfl_down_sync(0xffffffffu, v, o);
    int tid = threadIdx.x;
    if ((tid & 31) == 0) sh[tid >> 5] = v;
    __syncthreads();
    if (tid == 0) sh[0] = sh[0] + sh[1] + sh[2] + sh[3];
    __syncthreads();
    float r = sh[0];
    __syncthreads();
    return r;
}

__device__ __forceinline__ float bred_max(float v, float* sh) {
#pragma unroll
    for (int o = 16; o; o >>= 1) v = fmaxf(v, __shfl_down_sync(0xffffffffu, v, o));
    int tid = threadIdx.x;
    if ((tid & 31) == 0) sh[tid >> 5] = v;
    __syncthreads();
    if (tid == 0) sh[0] = fmaxf(fmaxf(sh[0], sh[1]), fmaxf(sh[2], sh[3]));
    __syncthreads();
    float r = sh[0];
    __syncthreads();
    return r;
}

// ---------------- small kernels ----------------
__global__ void k_reset() {
    int t = blockIdx.x * blockDim.x + threadIdx.x;
    if (t < BB * NN) g_map[t] = -1;
    if (t < BB) g_cnt[t] = 0;
}

__global__ void k_pool1(const float* __restrict__ tok) {
    int b = blockIdx.x, c = blockIdx.y, h = threadIdx.x;
    const float* p = tok + ((size_t)(b * NN + c * 128)) * HH + h;
    float s = 0.f;
#pragma unroll 8
    for (int n = 0; n < 128; n++) s += p[(size_t)n * HH];
    g_ppart[(b * 32 + c) * HH + h] = s;
}

__global__ void k_pool2() {
    int b = blockIdx.x, h = threadIdx.x;
    float s = 0.f;
#pragma unroll
    for (int c = 0; c < 32; c++) s += g_ppart[(b * 32 + c) * HH + h];
    g_pooled[b * HH + h] = s * (1.f / NN);
}

__global__ void k_gate(const float* __restrict__ lg, const float* __restrict__ lb,
                       const float* __restrict__ w, const float* __restrict__ wb) {
    __shared__ float sh[4];
    int b = blockIdx.x, tid = threadIdx.x;
    const float* x = g_pooled + b * HH;
    float v0 = x[tid], v1 = x[tid + 128], v2 = x[tid + 256], v3 = x[tid + 384];
    float s = bred_sum(v0 + v1 + v2 + v3, sh);
    float q = bred_sum(v0 * v0 + v1 * v1 + v2 * v2 + v3 * v3, sh);
    float mean = s * (1.f / HH);
    float var = q * (1.f / HH) - mean * mean;
    float rstd = rsqrtf(var + LNEPS);
    float d = ((v0 - mean) * rstd * lg[tid] + lb[tid]) * w[tid]
            + ((v1 - mean) * rstd * lg[tid + 128] + lb[tid + 128]) * w[tid + 128]
            + ((v2 - mean) * rstd * lg[tid + 256] + lb[tid + 256]) * w[tid + 256]
            + ((v3 - mean) * rstd * lg[tid + 384] + lb[tid + 384]) * w[tid + 384];
    d = bred_sum(d, sh);
    if (tid == 0) g_gate[b] = 1.f / (1.f + expf(-(d + wb[0])));
}

__global__ void k_sal(const float* __restrict__ tok, const float* __restrict__ lg,
                      const float* __restrict__ lb, const float* __restrict__ w,
                      const float* __restrict__ wb) {
    __shared__ float sh[4];
    int t = blockIdx.x, tid = threadIdx.x;
    const float* x = tok + (size_t)t * HH;
    float v0 = x[tid], v1 = x[tid + 128], v2 = x[tid + 256], v3 = x[tid + 384];
    float s = bred_sum(v0 + v1 + v2 + v3, sh);
    float q = bred_sum(v0 * v0 + v1 * v1 + v2 * v2 + v3 * v3, sh);
    float mean = s * (1.f / HH);
    float var = q * (1.f / HH) - mean * mean;
    float rstd = rsqrtf(var + LNEPS);
    float d = ((v0 - mean) * rstd * lg[tid] + lb[tid]) * w[tid]
            + ((v1 - mean) * rstd * lg[tid + 128] + lb[tid + 128]) * w[tid + 128]
            + ((v2 - mean) * rstd * lg[tid + 256] + lb[tid + 256]) * w[tid + 256]
            + ((v3 - mean) * rstd * lg[tid + 384] + lb[tid + 384]) * w[tid + 384];
    d = bred_sum(d, sh);
    if (tid == 0) g_sal[t] = d + wb[0];
}

__global__ void k_topk() {
    __shared__ float sh[NN];
    int b = blockIdx.x;
    for (int j = threadIdx.x; j < NN; j += 256) sh[j] = g_sal[b * NN + j];
    __syncthreads();
    int i = blockIdx.y * 256 + threadIdx.x;
    float si = sh[i];
    int cnt = 0;
    for (int j = 0; j < NN; j++) {
        float sj = sh[j];
        cnt += (sj > si) || (sj == si && j < i);
    }
    if (cnt < MM) {
        int p = atomicAdd(&g_cnt[b], 1);
        g_idx[b * MM + p] = i;
        g_map[b * NN + i] = p;
    }
}

__global__ void k_gather(const float* __restrict__ tok) {
    int t = blockIdx.x;
    int b = t >> 9;
    const float4* src = (const float4*)(tok + ((size_t)b * NN + g_idx[t]) * HH);
    float4* dst = (float4*)(g_sel + (size_t)t * HH);
    dst[threadIdx.x] = src[threadIdx.x];
}

// ---------------- BF16 tensor-core GEMM (double-buffered) ----------------
__device__ __forceinline__ uint32_t pack_bf(float lo, float hi) {
    __nv_bfloat162 h = __floats2bfloat162_rn(lo, hi);
    return *reinterpret_cast<uint32_t*>(&h);
}

__device__ __forceinline__ void mma16(float* d, const uint32_t* a, const uint32_t* b) {
    asm volatile(
        "mma.sync.aligned.m16n8k16.row.col.f32.bf16.bf16.f32 "
        "{%0,%1,%2,%3}, {%4,%5,%6,%7}, {%8,%9}, {%0,%1,%2,%3};"
        : "+f"(d[0]), "+f"(d[1]), "+f"(d[2]), "+f"(d[3])
        : "r"(a[0]), "r"(a[1]), "r"(a[2]), "r"(a[3]), "r"(b[0]), "r"(b[1]));
}

// C[m,n] = scale * sum_k A[m,k]*B[n,k] + bias[n]
// A: [M][K] stride lda; B: [N][K] stride ldb. Batch z = z1*zInner + z2.
// K tile = 32 floats (16 bf16x2 u32 cols), smem row stride 20 u32 (conflict-free).
template <int MT, int NT, int BWM, int BWN>
__global__ void __launch_bounds__(256, 2)
k_gemm_bf(const float* __restrict__ A, const float* __restrict__ B,
          const float* __restrict__ bias, float* __restrict__ C,
          int K, int lda, int ldb, int ldc, int zInner,
          long aS1, long aS2, long bS1, long bS2, long cS1, long cS2,
          float scale) {
    constexpr int WM = MT / BWM, WN = NT / BWN;
    constexpr int AM = WM / 16, BN = WN / 8;
    constexpr int NA = MT / 32, NB = NT / 32;
    __shared__ uint32_t As[2][MT][20];
    __shared__ uint32_t Bs[2][NT][20];

    int z = blockIdx.z;
    const float* Ab = A + (long)(z / zInner) * aS1 + (long)(z % zInner) * aS2;
    const float* Bb = B + (long)(z / zInner) * bS1 + (long)(z % zInner) * bS2;
    float* Cb = C + (long)(z / zInner) * cS1 + (long)(z % zInner) * cS2;

    int m0 = blockIdx.y * MT, n0 = blockIdx.x * NT;
    int tid = threadIdx.x, lane = tid & 31, wid = tid >> 5;
    int wm = (wid / BWN) * WM, wn = (wid % BWN) * WN;

    float acc[AM][BN][4];
#pragma unroll
    for (int i = 0; i < AM; i++)
#pragma unroll
        for (int j = 0; j < BN; j++) {
            acc[i][j][0] = 0.f; acc[i][j][1] = 0.f;
            acc[i][j][2] = 0.f; acc[i][j][3] = 0.f;
        }

    int lr = tid >> 3;            // 0..31
    int lk = (tid & 7) << 2;      // float col 0..28
    int lc = (tid & 7) << 1;      // u32 col 0..14

    float4 ar[NA], br[NB];

    auto loadT = [&](int k0) {
#pragma unroll
        for (int i = 0; i < NA; i++)
            ar[i] = *(const float4*)(Ab + (long)(m0 + lr + 32 * i) * lda + k0 + lk);
#pragma unroll
        for (int i = 0; i < NB; i++)
            br[i] = *(const float4*)(Bb + (long)(n0 + lr + 32 * i) * ldb + k0 + lk);
    };
    auto storeT = [&](int buf) {
#pragma unroll
        for (int i = 0; i < NA; i++) {
            As[buf][lr + 32 * i][lc]     = pack_bf(ar[i].x, ar[i].y);
            As[buf][lr + 32 * i][lc + 1] = pack_bf(ar[i].z, ar[i].w);
        }
#pragma unroll
        for (int i = 0; i < NB; i++) {
            Bs[buf][lr + 32 * i][lc]     = pack_bf(br[i].x, br[i].y);
            Bs[buf][lr + 32 * i][lc + 1] = pack_bf(br[i].z, br[i].w);
        }
    };

    int nk = K >> 5;
    loadT(0);
    storeT(0);
    __syncthreads();

    for (int kt = 0; kt < nk; kt++) {
        int buf = kt & 1;
        if (kt + 1 < nk) loadT((kt + 1) << 5);
#pragma unroll
        for (int ks = 0; ks < 2; ks++) {
            int cb = ks * 8 + (lane & 3);
            uint32_t af[AM][4];
#pragma unroll
            for (int i = 0; i < AM; i++) {
                int r = wm + i * 16 + (lane >> 2);
                af[i][0] = As[buf][r][cb];
                af[i][1] = As[buf][r + 8][cb];
                af[i][2] = As[buf][r][cb + 4];
                af[i][3] = As[buf][r + 8][cb + 4];
            }
            uint32_t bfr[BN][2];
#pragma unroll
            for (int j = 0; j < BN; j++) {
                int nr = wn + j * 8 + (lane >> 2);
                bfr[j][0] = Bs[buf][nr][cb];
                bfr[j][1] = Bs[buf][nr][cb + 4];
            }
#pragma unroll
            for (int i = 0; i < AM; i++)
#pragma unroll
                for (int j = 0; j < BN; j++)
                    mma16(acc[i][j], af[i], bfr[j]);
        }
        if (kt + 1 < nk) storeT(buf ^ 1);
        __syncthreads();
    }

#pragma unroll
    for (int i = 0; i < AM; i++) {
        int r0 = m0 + wm + i * 16 + (lane >> 2);
#pragma unroll
        for (int j = 0; j < BN; j++) {
            int c0 = n0 + wn + j * 8 + ((lane & 3) << 1);
            float b0 = 0.f, b1 = 0.f;
            if (bias) { b0 = bias[c0]; b1 = bias[c0 + 1]; }
            float2 o0, o1;
            o0.x = acc[i][j][0] * scale + b0;
            o0.y = acc[i][j][1] * scale + b1;
            o1.x = acc[i][j][2] * scale + b0;
            o1.y = acc[i][j][3] * scale + b1;
            *(float2*)(Cb + (long)r0 * ldc + c0) = o0;
            *(float2*)(Cb + (long)(r0 + 8) * ldc + c0) = o1;
        }
    }
}

// transpose V chunk of qkv into g_vt[z][64][512]
__global__ void k_vt(const float* __restrict__ qkv) {
    __shared__ float t[32][65];
    int z = blockIdx.x, b = z >> 3, h = z & 7;
    int m0 = blockIdx.y << 5;
    int d = threadIdx.x & 63, ml = threadIdx.x >> 6;
    const float* src = qkv + (size_t)(b * MM + m0) * (3 * HH) + 2 * HH + h * 64 + d;
#pragma unroll
    for (int i = 0; i < 8; i++)
        t[ml + 4 * i][d] = src[(size_t)(ml + 4 * i) * (3 * HH)];
    __syncthreads();
    int m = threadIdx.x & 31, dl = threadIdx.x >> 5;
    float* dst = g_vt + (size_t)z * (64 * MM) + m0 + m;
#pragma unroll
    for (int j = 0; j < 8; j++)
        dst[(size_t)(dl + 8 * j) * MM] = t[m][dl + 8 * j];
}

__global__ void k_softmax() {
    __shared__ float sh[4];
    size_t row = blockIdx.x;
    float* p = g_scores + row * MM;
    int tid = threadIdx.x;
    float v0 = p[tid], v1 = p[tid + 128], v2 = p[tid + 256], v3 = p[tid + 384];
    float mx = bred_max(fmaxf(fmaxf(v0, v1), fmaxf(v2, v3)), sh);
    float e0 = __expf(v0 - mx), e1 = __expf(v1 - mx), e2 = __expf(v2 - mx), e3 = __expf(v3 - mx);
    float sum = bred_sum(e0 + e1 + e2 + e3, sh);
    float inv = 1.f / sum;
    p[tid] = e0 * inv; p[tid + 128] = e1 * inv;
    p[tid + 256] = e2 * inv; p[tid + 384] = e3 * inv;
}

__global__ void k_lnres(const float* __restrict__ lg, const float* __restrict__ lb) {
    __shared__ float sh[4];
    int t = blockIdx.x, tid = threadIdx.x;
    float* r = g_rel + (size_t)t * HH;
    const float* s = g_sel + (size_t)t * HH;
    float v0 = s[tid] + r[tid];
    float v1 = s[tid + 128] + r[tid + 128];
    float v2 = s[tid + 256] + r[tid + 256];
    float v3 = s[tid + 384] + r[tid + 384];
    float su = bred_sum(v0 + v1 + v2 + v3, sh);
    float q = bred_sum(v0 * v0 + v1 * v1 + v2 * v2 + v3 * v3, sh);
    float mean = su * (1.f / HH);
    float var = q * (1.f / HH) - mean * mean;
    float rstd = rsqrtf(var + LNEPS);
    r[tid]       = (v0 - mean) * rstd * lg[tid]       + lb[tid];
    r[tid + 128] = (v1 - mean) * rstd * lg[tid + 128] + lb[tid + 128];
    r[tid + 256] = (v2 - mean) * rstd * lg[tid + 256] + lb[tid + 256];
    r[tid + 384] = (v3 - mean) * rstd * lg[tid + 384] + lb[tid + 384];
}

// out[row] = tok[row] + (selected ? gate * rel[slot] : 0)  — full-tensor pass
__global__ void k_final(const float* __restrict__ tok, float* __restrict__ out) {
    int row = blockIdx.x;
    int b = row >> 12;
    int m = g_map[row];
    int tid = threadIdx.x;
    const float4* src = (const float4*)(tok + (size_t)row * HH);
    float4* dst = (float4*)(out + (size_t)row * HH);
    float4 v = src[tid];
    if (m >= 0) {
        float gp = g_gate[b];
        const float4* r = (const float4*)(g_rel + ((size_t)b * MM + m) * HH);
        float4 rv = r[tid];
        v.x += gp * rv.x; v.y += gp * rv.y;
        v.z += gp * rv.z; v.w += gp * rv.w;
    }
    dst[tid] = v;
}

// ---------------- launch ----------------
extern "C" void kernel_launch(void* const* d_in, const int* in_sizes, int n_in,
                              void* d_out, int out_size) {
    const float* tok        = (const float*)d_in[0];
    const float* gate_ln_g  = (const float*)d_in[1];
    const float* gate_ln_b  = (const float*)d_in[2];
    const float* gate_w     = (const float*)d_in[3];
    const float* gate_b     = (const float*)d_in[4];
    const float* sal_ln_g   = (const float*)d_in[5];
    const float* sal_ln_b   = (const float*)d_in[6];
    const float* sal_w      = (const float*)d_in[7];
    const float* sal_b      = (const float*)d_in[8];
    const float* in_proj_w  = (const float*)d_in[9];
    const float* in_proj_b  = (const float*)d_in[10];
    const float* out_proj_w = (const float*)d_in[11];
    const float* out_proj_b = (const float*)d_in[12];
    const float* rel_ln_g   = (const float*)d_in[13];
    const float* rel_ln_b   = (const float*)d_in[14];
    float* out = (float*)d_out;

    void *p_sel_v, *p_qkv_v, *p_scores_v, *p_attn_v, *p_rel_v, *p_vt_v;
    cudaGetSymbolAddress(&p_sel_v, g_sel);
    cudaGetSymbolAddress(&p_qkv_v, g_qkv);
    cudaGetSymbolAddress(&p_scores_v, g_scores);
    cudaGetSymbolAddress(&p_attn_v, g_attn);
    cudaGetSymbolAddress(&p_rel_v, g_rel);
    cudaGetSymbolAddress(&p_vt_v, g_vt);
    float* p_sel = (float*)p_sel_v;
    float* p_qkv = (float*)p_qkv_v;
    float* p_scores = (float*)p_scores_v;
    float* p_attn = (float*)p_attn_v;
    float* p_rel = (float*)p_rel_v;
    float* p_vt = (float*)p_vt_v;

    k_reset<<<BB * NN / 256, 256>>>();
    k_pool1<<<dim3(BB, 32), 512>>>(tok);
    k_pool2<<<BB, 512>>>();
    k_gate<<<BB, 128>>>(gate_ln_g, gate_ln_b, gate_w, gate_b);
    k_sal<<<BB * NN, 128>>>(tok, sal_ln_g, sal_ln_b, sal_w, sal_b);
    k_topk<<<dim3(BB, NN / 256), 256>>>();
    k_gather<<<BB * MM, 128>>>(tok);

    // qkv = sel @ in_proj_w^T + in_proj_b : M=8192, N=1536, K=512
    k_gemm_bf<128, 128, 2, 4><<<dim3(12, 64, 1), 256>>>(
        p_sel, in_proj_w, in_proj_b, p_qkv,
        HH, HH, HH, 3 * HH, 1, 0L, 0L, 0L, 0L, 0L, 0L, 1.f);

    // scores = q @ k^T / 8 per (b,h): M=512, N=512, K=64
    k_gemm_bf<128, 128, 2, 4><<<dim3(4, 4, BB * NHEAD), 256>>>(
        p_qkv, p_qkv + HH, (const float*)0, p_scores,
        64, 3 * HH, 3 * HH, MM, NHEAD,
        (long)MM * 3 * HH, 64L, (long)MM * 3 * HH, 64L,
        (long)NHEAD * MM * MM, (long)MM * MM, 0.125f);

    k_softmax<<<BB * NHEAD * MM, 128>>>();
    k_vt<<<dim3(BB * NHEAD, MM / 32), 256>>>(p_qkv);

    // attn_out = attn @ v per (b,h): M=512, N=64, K=512 (B = V^T in [N][K])
    k_gemm_bf<128, 64, 4, 2><<<dim3(1, 4, BB * NHEAD), 256>>>(
        p_scores, p_vt, (const float*)0, p_attn,
        MM, MM, MM, HH, NHEAD,
        (long)NHEAD * MM * MM, (long)MM * MM,
        (long)NHEAD * 64 * MM, (long)64 * MM,
        (long)MM * HH, 64L, 1.f);

    // rel = attn_out @ out_proj_w^T + out_proj_b : M=8192, N=512, K=512
    k_gemm_bf<128, 128, 2, 4><<<dim3(4, 64, 1), 256>>>(
        p_attn, out_proj_w, out_proj_b, p_rel,
        HH, HH, HH, HH, 1, 0L, 0L, 0L, 0L, 0L, 0L, 1.f);

    k_lnres<<<BB * MM, 128>>>(rel_ln_g, rel_ln_b);
    k_final<<<BB * NN, 128>>>(tok, out);
}